// round 1
// baseline (speedup 1.0000x reference)
#include <cuda_runtime.h>
#include <cstdint>

static constexpr int NG      = 16;
static constexpr int NPG     = 4096;
static constexpr int NN      = NG * NPG;     // 65536 nodes
static constexpr int EE      = 1048576;      // edges
static constexpr int H       = 32;           // hidden
static constexpr int FC1_IN  = NPG * H;      // 131072
static constexpr int FC1_OUT = 256;
static constexpr int FC2_OUT = 64;

// -------- scratch (device globals; no allocation allowed) --------
__device__ int   g_src[EE];
__device__ int   g_dst[EE];
__device__ float g_deg[NN];
__device__ float g_dinv[NN];
__device__ float g_hs [NN * H];   // scaled features h * dinv  (gather source)
__device__ float g_acc[NN * H];   // accumulator (init = hs for self-loop)
__device__ float g_t1 [NG * FC1_OUT];
__device__ int   g_is64;

// -------- edge dtype detection: int64 buffers have all odd 32-bit words == 0
__global__ void detect_kernel(const unsigned int* __restrict__ w) {
    if (threadIdx.x == 0 && blockIdx.x == 0) {
        int is64 = 1;
        for (int i = 1; i < 512; i += 2)
            if (w[i] != 0u) { is64 = 0; break; }
        g_is64 = is64;
    }
}

__global__ void zero_deg_kernel() {
    int i = blockIdx.x * blockDim.x + threadIdx.x;
    if (i < NN) g_deg[i] = 0.0f;
}

__global__ void prep_edges_kernel(const void* __restrict__ eiraw) {
    int e = blockIdx.x * blockDim.x + threadIdx.x;
    if (e >= EE) return;
    int s, d;
    if (g_is64) {
        const long long* p = (const long long*)eiraw;
        s = (int)p[e];
        d = (int)p[EE + e];
    } else {
        const int* p = (const int*)eiraw;
        s = p[e];
        d = p[EE + e];
    }
    g_src[e] = s;
    g_dst[e] = d;
    atomicAdd(&g_deg[d], 1.0f);
}

__global__ void dinv_kernel() {
    int i = blockIdx.x * blockDim.x + threadIdx.x;
    if (i < NN) g_dinv[i] = rsqrtf(g_deg[i] + 1.0f);
}

// -------- per-node dense transform --------
// FIRST:  a = x[n]                       (KIN = 16)
// !FIRST: a = relu(dinv[n]*acc[n] + b)   (KIN = 32)
// then hs = (a @ W) * dinv[n]; acc = hs (self-loop init)
template<int KIN, bool FIRST>
__global__ void transform_kernel(const float* __restrict__ in_x,
                                 const float* __restrict__ W,
                                 const float* __restrict__ b_prev) {
    __shared__ float Ws[KIN * 32];
    int tid = threadIdx.x;
    for (int i = tid; i < KIN * 32; i += blockDim.x) Ws[i] = W[i];
    __syncthreads();

    int warp = tid >> 5, lane = tid & 31;
    int n = blockIdx.x * 8 + warp;
    float dv = g_dinv[n];
    float a;
    if (FIRST) {
        a = (lane < KIN) ? in_x[n * KIN + lane] : 0.0f;
    } else {
        a = fmaxf(dv * g_acc[n * 32 + lane] + b_prev[lane], 0.0f);
    }
    float o = 0.0f;
#pragma unroll
    for (int k = 0; k < KIN; k++)
        o = fmaf(__shfl_sync(0xffffffffu, a, k), Ws[k * 32 + lane], o);
    float hs = o * dv;
    g_hs [n * 32 + lane] = hs;
    g_acc[n * 32 + lane] = hs;
}

// -------- edge scatter: acc[dst] += hs[src], 8 threads/edge, v4 reductions --
__global__ void scatter_kernel() {
    int t = blockIdx.x * blockDim.x + threadIdx.x;
    int e = t >> 3;
    if (e >= EE) return;
    int j = t & 7;
    int s = g_src[e], d = g_dst[e];
    float4 v = *reinterpret_cast<const float4*>(g_hs + s * 32 + j * 4);
    float* p = g_acc + d * 32 + j * 4;
    asm volatile("red.global.add.v4.f32 [%0], {%1,%2,%3,%4};"
                 :: "l"(p), "f"(v.x), "f"(v.y), "f"(v.z), "f"(v.w)
                 : "memory");
}

__global__ void zero_t1_kernel() {
    int i = blockIdx.x * blockDim.x + threadIdx.x;
    if (i < NG * FC1_OUT) g_t1[i] = 0.0f;
}

// -------- fc1: t1[g][o] = sum_i relu3(h)[g][i] * fc1_w[i][o] --------
// Each block owns a CHUNK-slice of i for ALL 16 graphs, so fc1_w is read once.
__global__ void fc1_kernel(const float* __restrict__ fc1_w,
                           const float* __restrict__ b3) {
    constexpr int CHUNK = 512;
    __shared__ float a_s[NG * CHUNK];          // 32 KB, [g][i]
    int t  = threadIdx.x;                      // output column 0..255
    int i0 = blockIdx.x * CHUNK;

    // load + fused layer-3 activation: a = relu(dinv*acc + b3)
    for (int idx = t; idx < NG * CHUNK; idx += 256) {
        int g  = idx >> 9;            // / CHUNK
        int i  = idx & (CHUNK - 1);
        int gi = i0 + i;
        int f  = gi & 31;
        int node = g * NPG + (gi >> 5);
        a_s[idx] = fmaxf(g_dinv[node] * g_acc[g * FC1_IN + gi] + b3[f], 0.0f);
    }
    __syncthreads();

    float r[NG];
#pragma unroll
    for (int g = 0; g < NG; g++) r[g] = 0.0f;

    for (int i = 0; i < CHUNK; i += 4) {
        long base = (long)(i0 + i) * FC1_OUT + t;
        float w0 = fc1_w[base];
        float w1 = fc1_w[base + FC1_OUT];
        float w2 = fc1_w[base + 2 * FC1_OUT];
        float w3 = fc1_w[base + 3 * FC1_OUT];
#pragma unroll
        for (int g = 0; g < NG; g++) {
            float4 av = *reinterpret_cast<const float4*>(&a_s[g * CHUNK + i]);
            r[g] = fmaf(av.x, w0, r[g]);
            r[g] = fmaf(av.y, w1, r[g]);
            r[g] = fmaf(av.z, w2, r[g]);
            r[g] = fmaf(av.w, w3, r[g]);
        }
    }
#pragma unroll
    for (int g = 0; g < NG; g++)
        atomicAdd(&g_t1[g * FC1_OUT + t], r[g]);
}

// -------- fc2: out[g][o] = relu(t1+b1) @ fc2_w + fc2_b, single block -------
__global__ void fc2_kernel(const float* __restrict__ fc1_b,
                           const float* __restrict__ fc2_w,
                           const float* __restrict__ fc2_b,
                           float* __restrict__ out) {
    __shared__ float s[NG * FC1_OUT];          // 16 KB
    int t = threadIdx.x;                        // 0..1023
    for (int idx = t; idx < NG * FC1_OUT; idx += 1024) {
        int k = idx & (FC1_OUT - 1);
        s[idx] = fmaxf(g_t1[idx] + fc1_b[k], 0.0f);
    }
    __syncthreads();
    int g = t >> 6, o = t & 63;
    float acc = fc2_b[o];
#pragma unroll 8
    for (int k = 0; k < FC1_OUT; k++)
        acc = fmaf(s[g * FC1_OUT + k], fc2_w[k * FC2_OUT + o], acc);
    out[g * FC2_OUT + o] = acc;
}

extern "C" void kernel_launch(void* const* d_in, const int* in_sizes, int n_in,
                              void* d_out, int out_size) {
    const float* x     = (const float*)d_in[0];
    const void*  ei    = d_in[1];
    const float* W1    = (const float*)d_in[2];
    const float* b1    = (const float*)d_in[3];
    const float* W2    = (const float*)d_in[4];
    const float* b2    = (const float*)d_in[5];
    const float* W3    = (const float*)d_in[6];
    const float* b3    = (const float*)d_in[7];
    const float* fc1_w = (const float*)d_in[8];
    const float* fc1_b = (const float*)d_in[9];
    const float* fc2_w = (const float*)d_in[10];
    const float* fc2_b = (const float*)d_in[11];
    float* out = (float*)d_out;

    detect_kernel<<<1, 32>>>((const unsigned int*)ei);
    zero_deg_kernel<<<NN / 256, 256>>>();
    prep_edges_kernel<<<EE / 256, 256>>>(ei);
    dinv_kernel<<<NN / 256, 256>>>();

    transform_kernel<16, true ><<<NN / 8, 256>>>(x, W1, nullptr);
    scatter_kernel<<<(EE * 8) / 256, 256>>>();
    transform_kernel<32, false><<<NN / 8, 256>>>(nullptr, W2, b1);
    scatter_kernel<<<(EE * 8) / 256, 256>>>();
    transform_kernel<32, false><<<NN / 8, 256>>>(nullptr, W3, b2);
    scatter_kernel<<<(EE * 8) / 256, 256>>>();

    zero_t1_kernel<<<(NG * FC1_OUT + 255) / 256, 256>>>();
    fc1_kernel<<<FC1_IN / 512, 256>>>(fc1_w, b3);
    fc2_kernel<<<1, 1024>>>(fc1_b, fc2_w, fc2_b, out);
}

// round 3
// speedup vs baseline: 1.0768x; 1.0768x over previous
#include <cuda_runtime.h>
#include <cstdint>

static constexpr int NG      = 16;
static constexpr int NPG     = 4096;
static constexpr int NN      = NG * NPG;     // 65536 nodes
static constexpr int EE      = 1048576;      // edges
static constexpr int H       = 32;           // hidden
static constexpr int FC1_IN  = NPG * H;      // 131072
static constexpr int FC1_OUT = 256;
static constexpr int FC2_OUT = 64;

// -------- scratch (device globals; no allocation allowed) --------
__device__ int   g_degi[NN];
__device__ int   g_cnt [NN];
__device__ int   g_off [NN];
__device__ int   g_bsum[256];
__device__ float g_dinv[NN];
__device__ int   g_eidx[EE];        // CSR: src indices grouped by dst
__device__ float g_h0 [NN * H];
__device__ float g_h1 [NN * H];
__device__ float g_act[NN * H];     // final pre-activated features for fc1
__device__ float g_t1 [NG * FC1_OUT];
__device__ int   g_is64;

// -------- edge dtype detection: int64 buffers have all odd 32-bit words == 0
__global__ void detect_kernel(const unsigned int* __restrict__ w) {
    if (threadIdx.x == 0 && blockIdx.x == 0) {
        int is64 = 1;
        for (int i = 1; i < 512; i += 2)
            if (w[i] != 0u) { is64 = 0; break; }
        g_is64 = is64;
    }
}

__global__ void zero_kernel() {
    int i = blockIdx.x * blockDim.x + threadIdx.x;
    if (i < NN) { g_degi[i] = 0; g_cnt[i] = 0; }
    if (i < NG * FC1_OUT) g_t1[i] = 0.0f;
}

__global__ void deg_kernel(const void* __restrict__ eiraw) {
    int e = blockIdx.x * blockDim.x + threadIdx.x;
    if (e >= EE) return;
    int d;
    if (g_is64) d = (int)((const long long*)eiraw)[EE + e];
    else        d = ((const int*)eiraw)[EE + e];
    atomicAdd(&g_degi[d], 1);
}

// block-level inclusive scan of degrees (256 blocks x 256); also emits dinv
__global__ void scan1_kernel() {
    __shared__ int sh[256];
    int t = threadIdx.x;
    int i = blockIdx.x * 256 + t;
    int v = g_degi[i];
    g_dinv[i] = rsqrtf((float)v + 1.0f);
    sh[t] = v;
    __syncthreads();
#pragma unroll
    for (int off = 1; off < 256; off <<= 1) {
        int x = (t >= off) ? sh[t - off] : 0;
        __syncthreads();
        sh[t] += x;
        __syncthreads();
    }
    g_off[i] = sh[t] - v;                       // block-local exclusive
    if (t == 255) g_bsum[blockIdx.x] = sh[t];   // block total
}

__global__ void scan2_kernel() {                // exclusive scan of block sums
    __shared__ int sh[256];
    int t = threadIdx.x;
    int v = g_bsum[t];
    sh[t] = v;
    __syncthreads();
#pragma unroll
    for (int off = 1; off < 256; off <<= 1) {
        int x = (t >= off) ? sh[t - off] : 0;
        __syncthreads();
        sh[t] += x;
        __syncthreads();
    }
    g_bsum[t] = sh[t] - v;
}

__global__ void scan3_kernel() {                // add block bases
    int i = blockIdx.x * blockDim.x + threadIdx.x;
    if (i < NN) g_off[i] += g_bsum[i >> 8];
}

__global__ void fill_kernel(const void* __restrict__ eiraw) {
    int e = blockIdx.x * blockDim.x + threadIdx.x;
    if (e >= EE) return;
    int s, d;
    if (g_is64) {
        const long long* p = (const long long*)eiraw;
        s = (int)p[e];
        d = (int)p[EE + e];
    } else {
        const int* p = (const int*)eiraw;
        s = p[e];
        d = p[EE + e];
    }
    int pos = g_off[d] + atomicAdd(&g_cnt[d], 1);
    g_eidx[pos] = s;
}

// -------- layer 1 dense transform: hs = (x @ W1) * dinv --------
__global__ void transform1_kernel(const float* __restrict__ in_x,
                                  const float* __restrict__ W) {
    __shared__ float Ws[16 * 32];
    int tid = threadIdx.x;
    for (int i = tid; i < 16 * 32; i += 256) Ws[i] = W[i];
    __syncthreads();
    int warp = tid >> 5, lane = tid & 31;
    int n = blockIdx.x * 8 + warp;
    float a = (lane < 16) ? in_x[n * 16 + lane] : 0.0f;
    float o = 0.0f;
#pragma unroll
    for (int k = 0; k < 16; k++)
        o = fmaf(__shfl_sync(0xffffffffu, a, k), Ws[k * 32 + lane], o);
    g_h0[n * 32 + lane] = o * g_dinv[n];
}

// -------- fused CSR aggregation + activation (+ next matmul) --------
// LAYER 0: in g_h0, out g_h1, fused matmul (mid layer)
// LAYER 1: in g_h1, out g_h0, fused matmul (mid layer)
// LAYER 2: in g_h0, out g_act, activation only (feeds fc1)
// NOTE: device globals are referenced INSIDE device code only (host-side
// symbol addresses are invalid — that was the round-2 bug).
template<int LAYER>
__global__ void agg_kernel(const float* __restrict__ W,
                           const float* __restrict__ b) {
    const float* hs_in = (LAYER == 1) ? g_h1 : g_h0;
    float* out = (LAYER == 0) ? g_h1 : (LAYER == 1) ? g_h0 : g_act;

    __shared__ float Ws[H * H];
    int tid = threadIdx.x;
    if (LAYER < 2) {
        for (int i = tid; i < H * H; i += 256) Ws[i] = W[i];
        __syncthreads();
    }
    int warp = tid >> 5, lane = tid & 31;
    int n = blockIdx.x * 8 + warp;
    int start = g_off[n];
    int end   = start + g_degi[n];
    const float* hp = hs_in + lane;
    float acc0 = hs_in[n * H + lane];   // self-loop term
    float acc1 = 0.f, acc2 = 0.f, acc3 = 0.f;
    for (int e0 = start; e0 < end; e0 += 32) {
        int cnt = min(32, end - e0);
        int my  = (lane < cnt) ? g_eidx[e0 + lane] : 0;
        int j = 0;
        for (; j + 4 <= cnt; j += 4) {
            int s0 = __shfl_sync(0xffffffffu, my, j);
            int s1 = __shfl_sync(0xffffffffu, my, j + 1);
            int s2 = __shfl_sync(0xffffffffu, my, j + 2);
            int s3 = __shfl_sync(0xffffffffu, my, j + 3);
            float v0 = hp[s0 * H], v1 = hp[s1 * H];
            float v2 = hp[s2 * H], v3 = hp[s3 * H];
            acc0 += v0; acc1 += v1; acc2 += v2; acc3 += v3;
        }
        for (; j < cnt; j++) {
            int s = __shfl_sync(0xffffffffu, my, j);
            acc0 += hp[s * H];
        }
    }
    float dv = g_dinv[n];
    float a = fmaxf(dv * ((acc0 + acc1) + (acc2 + acc3)) + b[lane], 0.0f);
    if (LAYER == 2) { out[n * H + lane] = a; return; }
    float o = 0.0f;
#pragma unroll
    for (int k = 0; k < H; k++)
        o = fmaf(__shfl_sync(0xffffffffu, a, k), Ws[k * H + lane], o);
    out[n * H + lane] = o * dv;
}

// -------- fc1: t1[g][o] += act-slice @ fc1_w-slice (weights read once) ----
__global__ void fc1_kernel(const float* __restrict__ fc1_w) {
    constexpr int CHUNK = 512;
    __shared__ float a_s[NG * CHUNK];           // 32 KB, [g][i]
    int t  = threadIdx.x;                        // output column 0..255
    int i0 = blockIdx.x * CHUNK;

    // coalesced float4 copy of the pre-activated slice for all 16 graphs
    for (int idx = t; idx < NG * (CHUNK / 4); idx += 256) {
        int g  = idx >> 7;                       // / (CHUNK/4)
        int i4 = idx & (CHUNK / 4 - 1);
        float4 v = *reinterpret_cast<const float4*>(g_act + g * FC1_IN + i0 + i4 * 4);
        *reinterpret_cast<float4*>(&a_s[g * CHUNK + i4 * 4]) = v;
    }
    __syncthreads();

    float r[NG];
#pragma unroll
    for (int g = 0; g < NG; g++) r[g] = 0.0f;

    for (int i = 0; i < CHUNK; i += 4) {
        long base = (long)(i0 + i) * FC1_OUT + t;
        float w0 = fc1_w[base];
        float w1 = fc1_w[base + FC1_OUT];
        float w2 = fc1_w[base + 2 * FC1_OUT];
        float w3 = fc1_w[base + 3 * FC1_OUT];
#pragma unroll
        for (int g = 0; g < NG; g++) {
            float4 av = *reinterpret_cast<const float4*>(&a_s[g * CHUNK + i]);
            r[g] = fmaf(av.x, w0, r[g]);
            r[g] = fmaf(av.y, w1, r[g]);
            r[g] = fmaf(av.z, w2, r[g]);
            r[g] = fmaf(av.w, w3, r[g]);
        }
    }
#pragma unroll
    for (int g = 0; g < NG; g++)
        atomicAdd(&g_t1[g * FC1_OUT + t], r[g]);
}

// -------- fc2: out = relu(t1 + fc1_b) @ fc2_w + fc2_b, single block -------
__global__ void fc2_kernel(const float* __restrict__ fc1_b,
                           const float* __restrict__ fc2_w,
                           const float* __restrict__ fc2_b,
                           float* __restrict__ out) {
    __shared__ float s[NG * FC1_OUT];            // 16 KB
    int t = threadIdx.x;                          // 0..1023
    for (int idx = t; idx < NG * FC1_OUT; idx += 1024) {
        int k = idx & (FC1_OUT - 1);
        s[idx] = fmaxf(g_t1[idx] + fc1_b[k], 0.0f);
    }
    __syncthreads();
    int g = t >> 6, o = t & 63;
    float acc = fc2_b[o];
#pragma unroll 8
    for (int k = 0; k < FC1_OUT; k++)
        acc = fmaf(s[g * FC1_OUT + k], fc2_w[k * FC2_OUT + o], acc);
    out[g * FC2_OUT + o] = acc;
}

extern "C" void kernel_launch(void* const* d_in, const int* in_sizes, int n_in,
                              void* d_out, int out_size) {
    const float* x     = (const float*)d_in[0];
    const void*  ei    = d_in[1];
    const float* W1    = (const float*)d_in[2];
    const float* b1    = (const float*)d_in[3];
    const float* W2    = (const float*)d_in[4];
    const float* b2    = (const float*)d_in[5];
    const float* W3    = (const float*)d_in[6];
    const float* b3    = (const float*)d_in[7];
    const float* fc1_w = (const float*)d_in[8];
    const float* fc1_b = (const float*)d_in[9];
    const float* fc2_w = (const float*)d_in[10];
    const float* fc2_b = (const float*)d_in[11];
    float* out = (float*)d_out;

    detect_kernel<<<1, 32>>>((const unsigned int*)ei);
    zero_kernel<<<NN / 256, 256>>>();
    deg_kernel<<<EE / 256, 256>>>(ei);
    scan1_kernel<<<256, 256>>>();
    scan2_kernel<<<1, 256>>>();
    scan3_kernel<<<NN / 256, 256>>>();
    fill_kernel<<<EE / 256, 256>>>(ei);

    transform1_kernel<<<NN / 8, 256>>>(x, W1);
    agg_kernel<0><<<NN / 8, 256>>>(W2, b1);
    agg_kernel<1><<<NN / 8, 256>>>(W3, b2);
    agg_kernel<2><<<NN / 8, 256>>>(nullptr, b3);

    fc1_kernel<<<256, 256>>>(fc1_w);
    fc2_kernel<<<1, 1024>>>(fc1_b, fc2_w, fc2_b, out);
}